// round 16
// baseline (speedup 1.0000x reference)
#include <cuda_runtime.h>
#include <cuda_fp16.h>
#include <cstdint>

#define T_DIM 8192
#define K_DIM 4096
#define N_DIM 4096
#define R_DIM 64
#define NGRP  8

// ---------------- static device scratch (alloc forbidden) -------------------
__device__ __half g_x16[(size_t)T_DIM * K_DIM];
__device__ __half g_w16[(size_t)N_DIM * K_DIM];
__device__ __half g_la16[(size_t)NGRP * R_DIM * K_DIM];
__device__ __half g_lb16[(size_t)NGRP * N_DIM * R_DIM];   // [g][n][r] transposed
__device__ __half g_sh16[(size_t)T_DIM * R_DIM];
__device__ int    g_flag;      // shrink-done counter
__device__ int    g_cnt[66];   // cvt progress: [0]=la, [1..64]=slices, [65]=lorab

// ---------------- asm helpers (base ISA only: sm_80-class) ------------------
__device__ __forceinline__ uint32_t smem_u32(const void* p) {
    uint32_t a;
    asm("{ .reg .u64 t; cvta.to.shared.u64 t, %1; cvt.u32.u64 %0, t; }"
        : "=r"(a) : "l"(p));
    return a;
}
#define CP16(dst, src) \
    asm volatile("cp.async.cg.shared.global [%0], [%1], 16;" :: "r"(dst), "l"(src))
#define CP_COMMIT() asm volatile("cp.async.commit_group;" ::: "memory")
#define CP_WAIT1()  asm volatile("cp.async.wait_group 1;"  ::: "memory")
#define CP_WAIT2()  asm volatile("cp.async.wait_group 2;"  ::: "memory")

#define LDSM4(d, addr) \
    asm volatile("ldmatrix.sync.aligned.m8n8.x4.shared.b16 {%0,%1,%2,%3}, [%4];" \
        : "=r"((d)[0]), "=r"((d)[1]), "=r"((d)[2]), "=r"((d)[3]) : "r"(addr))

#define MMA_F16(ac, a, b0, b1) \
    asm volatile("mma.sync.aligned.m16n8k16.row.col.f32.f16.f16.f32 " \
        "{%0,%1,%2,%3}, {%4,%5,%6,%7}, {%8,%9}, {%0,%1,%2,%3};" \
        : "+f"((ac)[0]), "+f"((ac)[1]), "+f"((ac)[2]), "+f"((ac)[3]) \
        : "r"((a)[0]), "r"((a)[1]), "r"((a)[2]), "r"((a)[3]), "r"(b0), "r"(b1))

// smem byte offset of 16B chunk (row, ch) within a tile of 128B rows (BK=64).
__device__ __forceinline__ uint32_t swz(int row, int ch) {
    return (uint32_t)((row << 7) | (((ch ^ (row & 7)) & 7) << 4));
}

__device__ __forceinline__ int find_group(const int* __restrict__ gl,
                                          int n_groups, int token) {
    int g = 0;
    while (g < n_groups - 1 && token >= gl[g]) g++;
    return g;
}

__global__ void reset_kernel() {
    if (threadIdx.x < 66) g_cnt[threadIdx.x] = 0;
    if (threadIdx.x == 66) g_flag = 0;
}

// =============================================================================
// Fused kernel. Grid layout (1-D, 2240 blocks; wave 1 = 296 slots covers all
// three producer/consumer classes simultaneously -> deadlock-free):
//   [0,128):    converters: la cvt -> x/W K-slices 0..63 -> lorab transpose.
//               Per-block in-order stages => g_cnt[i]==128 implies all earlier
//               stages complete (prefix-monotone).
//   [128,192):  shrink tiles (wait on cvt slices; release g_flag).
//   [192,2240): GEMM tiles (wait on cvt slices; LoRA chunk waits g_flag+lorab).
// =============================================================================
#define SH_STAGE 24576
#define SH_CHUNKS (K_DIM / 64)       // 64
#define MN_STAGE 32768
#define MN_BASEC (K_DIM / 64)        // 64 base chunks
#define MN_CHUNKS (MN_BASEC + 1)     // + 1 LoRA chunk
#define SMEM_BYTES 98304             // == 4*SH_STAGE == 3*MN_STAGE

__global__ __launch_bounds__(256, 2) void fused_main(
    const float* __restrict__ xf, const float* __restrict__ Wf,
    const float* __restrict__ laf, const float* __restrict__ lbf,
    const int* __restrict__ gl, int n_groups, float* __restrict__ out)
{
    extern __shared__ char smem[];
    uint32_t sb = smem_u32(smem);
    int tid = threadIdx.x, lane = tid & 31, w = tid >> 5;

    if (blockIdx.x < 128) {
        // ------------------------- converter path ---------------------------
        int bid = blockIdx.x;
        // stage 0: lora_a cvt (524288 float4 = 16/thread)
        {
            const float4* src = reinterpret_cast<const float4*>(laf);
            __half2* dst = reinterpret_cast<__half2*>(g_la16);
            #pragma unroll
            for (int it = 0; it < 16; it++) {
                size_t i = (size_t)it * 32768 + bid * 256 + tid;
                float4 v = src[i];
                dst[2 * i]     = __floats2half2_rn(v.x, v.y);
                dst[2 * i + 1] = __floats2half2_rn(v.z, v.w);
            }
            __threadfence(); __syncthreads();
            if (tid == 0) atomicAdd(&g_cnt[0], 1);
        }
        // stages 1..64: K-slice k of x (4 f4/thread) + W (2 f4/thread)
        const float4* xs = reinterpret_cast<const float4*>(xf);
        const float4* ws = reinterpret_cast<const float4*>(Wf);
        __half2* xd = reinterpret_cast<__half2*>(g_x16);
        __half2* wd = reinterpret_cast<__half2*>(g_w16);
        for (int k = 0; k < 64; k++) {
            #pragma unroll
            for (int it = 0; it < 4; it++) {
                int i = it * 32768 + bid * 256 + tid;   // 0..131071
                int r = i >> 4, s = i & 15;
                float4 v = xs[(size_t)r * 1024 + k * 16 + s];
                size_t h = (size_t)r * 2048 + k * 32 + s * 2;
                xd[h]     = __floats2half2_rn(v.x, v.y);
                xd[h + 1] = __floats2half2_rn(v.z, v.w);
            }
            #pragma unroll
            for (int it = 0; it < 2; it++) {
                int j = it * 32768 + bid * 256 + tid;   // 0..65535
                int r = j >> 4, s = j & 15;
                float4 v = ws[(size_t)r * 1024 + k * 16 + s];
                size_t h = (size_t)r * 2048 + k * 32 + s * 2;
                wd[h]     = __floats2half2_rn(v.x, v.y);
                wd[h + 1] = __floats2half2_rn(v.z, v.w);
            }
            __threadfence(); __syncthreads();
            if (tid == 0) atomicAdd(&g_cnt[k + 1], 1);
        }
        // stage 65: lorab transpose, 4 tiles/block
        float (*t)[65] = reinterpret_cast<float(*)[65]>(smem);
        for (int it = 0; it < 4; it++) {
            int tt = bid * 4 + it;      // 0..511
            int g = tt >> 6;
            int n0 = (tt & 63) * 64;
            __syncthreads();
            for (int idx = tid; idx < 4096; idx += 256) {
                int r = idx >> 6, n = idx & 63;
                t[n][r] = lbf[((size_t)g * R_DIM + r) * N_DIM + n0 + n];
            }
            __syncthreads();
            for (int idx = tid; idx < 4096; idx += 256) {
                int n = idx >> 6, r = idx & 63;
                g_lb16[((size_t)g * N_DIM + n0 + n) * R_DIM + r] =
                    __float2half_rn(t[n][r]);
            }
        }
        __threadfence(); __syncthreads();
        if (tid == 0) atomicAdd(&g_cnt[65], 1);
        return;
    }

    if (blockIdx.x < 192) {
        // ------------------------- shrink path ------------------------------
        int m_off = (w & 3) * 32, n_off = (w >> 2) * 32;
        int row0 = (blockIdx.x - 128) * 128;
        int g = find_group(gl, n_groups, row0);

        const __half* A = g_x16 + (size_t)row0 * K_DIM;
        const __half* B = g_la16 + (size_t)g * R_DIM * K_DIM;

        float acc[2][4][4];
        #pragma unroll
        for (int i = 0; i < 2; i++)
            #pragma unroll
            for (int j = 0; j < 4; j++)
                #pragma unroll
                for (int q = 0; q < 4; q++) acc[i][j][q] = 0.f;

        auto fill = [&](int s, int c) {
            uint32_t st = sb + s * SH_STAGE;
            #pragma unroll
            for (int it = 0; it < 6; it++) {
                int idx = tid + it * 256;
                if (idx < 1024) {
                    int row = idx >> 3, ch = idx & 7;
                    CP16(st + swz(row, ch),
                         A + (size_t)row * K_DIM + c * 64 + ch * 8);
                } else {
                    int u = idx - 1024;
                    int row = u >> 3, ch = u & 7;
                    CP16(st + 16384 + swz(row, ch),
                         B + (size_t)row * K_DIM + c * 64 + ch * 8);
                }
            }
        };

        // wait for la + slices 0..2 (prefix: cnt[3]==128 implies all earlier)
        if (tid == 0) while (atomicAdd(&g_cnt[3], 0) < 128) { }
        __syncthreads();
        __threadfence();

        fill(0, 0); CP_COMMIT();
        fill(1, 1); CP_COMMIT();
        fill(2, 2); CP_COMMIT();

        int d0 = 3;   // slices < d0 verified (tid0 only)
        for (int c = 0; c < SH_CHUNKS; c++) {
            CP_WAIT2();
            {
                int cc = c + 3;
                if (tid == 0 && cc < SH_CHUNKS && d0 <= cc) {
                    while (atomicAdd(&g_cnt[cc + 1], 0) < 128) { }
                    d0 = (atomicAdd(&g_cnt[64], 0) == 128) ? 64 : cc + 1;
                }
            }
            __syncthreads();
            uint32_t st = sb + (c & 3) * SH_STAGE;
            #pragma unroll
            for (int ks = 0; ks < 4; ks++) {
                uint32_t aa[2][4], bb[2][4];
                #pragma unroll
                for (int mt = 0; mt < 2; mt++) {
                    int row = m_off + mt * 16 + (lane & 15);
                    int ch = ks * 2 + (lane >> 4);
                    LDSM4(aa[mt], st + swz(row, ch));
                }
                #pragma unroll
                for (int p = 0; p < 2; p++) {
                    int row = n_off + p * 16 + (lane & 15);
                    int ch = ks * 2 + (lane >> 4);
                    LDSM4(bb[p], st + 16384 + swz(row, ch));
                }
                #pragma unroll
                for (int mt = 0; mt < 2; mt++)
                    #pragma unroll
                    for (int p = 0; p < 2; p++) {
                        MMA_F16(acc[mt][2 * p],     aa[mt], bb[p][0], bb[p][2]);
                        MMA_F16(acc[mt][2 * p + 1], aa[mt], bb[p][1], bb[p][3]);
                    }
            }
            if (c + 3 < SH_CHUNKS) fill((c + 3) & 3, c + 3);
            CP_COMMIT();
        }

        #pragma unroll
        for (int mt = 0; mt < 2; mt++)
            #pragma unroll
            for (int j = 0; j < 4; j++) {
                int row = row0 + m_off + mt * 16 + (lane >> 2);
                int col = n_off + j * 8 + ((lane & 3) << 1);
                *reinterpret_cast<__half2*>(g_sh16 + (size_t)row * R_DIM + col)
                    = __floats2half2_rn(acc[mt][j][0], acc[mt][j][1]);
                *reinterpret_cast<__half2*>(g_sh16 + (size_t)(row + 8) * R_DIM + col)
                    = __floats2half2_rn(acc[mt][j][2], acc[mt][j][3]);
            }
        __syncthreads();
        __threadfence();                     // release g_sh16 writes
        if (tid == 0) atomicAdd(&g_flag, 1);
        return;
    }

    // ----------------------------- GEMM path --------------------------------
    int b = blockIdx.x - 192;
    int col0 = (b & 31) * 128;
    int row0 = (b >> 5) * 128;
    int m_off = (w & 3) * 32, n_off = (w >> 2) * 64;
    int g = find_group(gl, n_groups, row0);

    float acc[2][8][4];
    #pragma unroll
    for (int i = 0; i < 2; i++)
        #pragma unroll
        for (int j = 0; j < 8; j++)
            #pragma unroll
            for (int q = 0; q < 4; q++) acc[i][j][q] = 0.f;

    // ---- hoisted LDSM addressing ----
    const int lr  = lane & 15;
    const int par = lane >> 4;
    const int r   = lr & 7;
    const uint32_t pbit = (uint32_t)((par ^ (r & 1)) << 4);
    const int rk = (r >> 1) & 3;
    uint32_t k_off[4];
    #pragma unroll
    for (int ks = 0; ks < 4; ks++) k_off[ks] = (uint32_t)(((ks ^ rk) & 3) << 5);
    uint32_t a_cst[2], b_cst[4];
    #pragma unroll
    for (int mt = 0; mt < 2; mt++)
        a_cst[mt] = (uint32_t)((m_off + mt * 16 + lr) << 7) + pbit;
    #pragma unroll
    for (int p = 0; p < 4; p++)
        b_cst[p] = 16384u + (uint32_t)((n_off + p * 16 + lr) << 7) + pbit;

    // ---- hoisted fill addressing (8 CP16s/thread: 4 A + 4 B) ----
    uint32_t s_off[8];
    int      g_off[8];
    #pragma unroll
    for (int it = 0; it < 8; it++) {
        int idx = tid + it * 256;
        if (idx < 1024) {
            int row = idx >> 3, ch = idx & 7;
            s_off[it] = swz(row, ch);
            g_off[it] = row * K_DIM + ch * 8;
        } else {
            int u = idx - 1024;
            int row = u >> 3, ch = u & 7;
            s_off[it] = 16384u + swz(row, ch);
            g_off[it] = row * K_DIM + ch * 8;
        }
    }
    const __half* pAf = g_x16 + (size_t)row0 * K_DIM;
    const __half* pBf = g_w16 + (size_t)col0 * K_DIM;

    auto fill_main = [&](uint32_t st) {
        #pragma unroll
        for (int it = 0; it < 4; it++)
            CP16(st + s_off[it], pAf + g_off[it]);
        #pragma unroll
        for (int it = 4; it < 8; it++)
            CP16(st + s_off[it], pBf + g_off[it]);
        pAf += 64; pBf += 64;
    };
    auto fill_lora = [&](uint32_t st) {
        const __half* pA = g_sh16 + (size_t)row0 * R_DIM;
        const __half* pB = g_lb16 + ((size_t)g * N_DIM + col0) * R_DIM;
        #pragma unroll
        for (int it = 0; it < 8; it++) {
            int idx = tid + it * 256;
            if (idx < 1024) {
                int row = idx >> 3, ch = idx & 7;
                CP16(st + swz(row, ch), pA + row * R_DIM + ch * 8);
            } else {
                int u = idx - 1024;
                int row = u >> 3, ch = u & 7;
                CP16(st + 16384u + swz(row, ch), pB + row * R_DIM + ch * 8);
            }
        }
    };

    // wait for slices 0,1 (cnt[2]==128; prefix implies la + slice 0)
    if (tid == 0) while (atomicAdd(&g_cnt[2], 0) < 128) { }
    __syncthreads();
    __threadfence();

    fill_main(sb);             CP_COMMIT();
    fill_main(sb + MN_STAGE);  CP_COMMIT();

    uint32_t st_c = sb;
    uint32_t st_f = sb + 2u * MN_STAGE;
    const uint32_t st_top = sb + 2u * MN_STAGE;

    int d0 = 2;   // slices < d0 verified (tid0 only)
    for (int c = 0; c < MN_CHUNKS; c++) {
        CP_WAIT1();
        {
            int cc = c + 2;
            if (tid == 0 && cc < MN_BASEC && d0 <= cc) {
                while (atomicAdd(&g_cnt[cc + 1], 0) < 128) { }
                d0 = (atomicAdd(&g_cnt[64], 0) == 128) ? 64 : cc + 1;
            }
        }
        __syncthreads();
        #pragma unroll
        for (int ks = 0; ks < 4; ks++) {
            uint32_t aa[2][4], bb[4][4];
            #pragma unroll
            for (int mt = 0; mt < 2; mt++)
                LDSM4(aa[mt], st_c + a_cst[mt] + k_off[ks]);
            #pragma unroll
            for (int p = 0; p < 4; p++)
                LDSM4(bb[p], st_c + b_cst[p] + k_off[ks]);
            #pragma unroll
            for (int mt = 0; mt < 2; mt++)
                #pragma unroll
                for (int p = 0; p < 4; p++) {
                    MMA_F16(acc[mt][2 * p],     aa[mt], bb[p][0], bb[p][2]);
                    MMA_F16(acc[mt][2 * p + 1], aa[mt], bb[p][1], bb[p][3]);
                }
        }
        if (c + 2 < MN_BASEC) {
            fill_main(st_f);
        } else if (c + 2 == MN_BASEC) {
            // acquire: shrink outputs + lorab transpose
            if (tid == 0) {
                while (atomicAdd(&g_flag, 0) < 64) { }
                while (atomicAdd(&g_cnt[65], 0) < 128) { }
            }
            __syncthreads();
            __threadfence();
            fill_lora(st_f);
        }
        CP_COMMIT();
        st_c = (st_c == st_top) ? sb : st_c + MN_STAGE;
        st_f = (st_f == st_top) ? sb : st_f + MN_STAGE;
    }

    #pragma unroll
    for (int mt = 0; mt < 2; mt++)
        #pragma unroll
        for (int j = 0; j < 8; j++) {
            int row = row0 + m_off + mt * 16 + (lane >> 2);
            int col = col0 + n_off + j * 8 + ((lane & 3) << 1);
            *reinterpret_cast<float2*>(out + (size_t)row * N_DIM + col)
                = make_float2(acc[mt][j][0], acc[mt][j][1]);
            *reinterpret_cast<float2*>(out + (size_t)(row + 8) * N_DIM + col)
                = make_float2(acc[mt][j][2], acc[mt][j][3]);
        }
}

// ---------------- launch -----------------------------------------------------
extern "C" void kernel_launch(void* const* d_in, const int* in_sizes, int n_in,
                              void* d_out, int out_size) {
    const float* x      = (const float*)d_in[0];
    const float* W      = (const float*)d_in[1];
    const float* lora_a = (const float*)d_in[2];
    const float* lora_b = (const float*)d_in[3];
    const int*   gl     = (const int*)d_in[4];
    const int n_groups  = in_sizes[4];
    float* out = (float*)d_out;

    cudaFuncSetAttribute(fused_main, cudaFuncAttributeMaxDynamicSharedMemorySize,
                         SMEM_BYTES);

    reset_kernel<<<1, 128>>>();
    fused_main<<<128 + 64 + (N_DIM / 128) * (T_DIM / 128), 256, SMEM_BYTES>>>(
        x, W, lora_a, lora_b, gl, n_groups, out);
}